// round 3
// baseline (speedup 1.0000x reference)
#include <cuda_runtime.h>
#include <math.h>

#define BB 2
#define SS 2048
#define HH 1024
#define NH 16
#define HD 64
#define MTOT (BB*SS)   // 4096

// Scratch (static device allocation — allowed)
__device__ float g_q[MTOT*HH];
__device__ float g_k[MTOT*HH];
__device__ float g_v[MTOT*HH];
__device__ float g_ctx[MTOT*HH];
__device__ float g_vsuf[BB*NH*65*HD];

// ---------------------------------------------------------------------------
// GEMM: C[m,n] = sum_k A[m,k] * W[n,k] + bias[n]   (NT, both K-contiguous)
// M=4096, N=1024, K=1024. 128x128 tile, BK=16, 256 threads, 8x8 microtile.
// blockIdx.z selects (W,bias,C) so QKV runs as one launch.
// ---------------------------------------------------------------------------
__global__ void __launch_bounds__(256) gemm_nt_bias(
    const float* __restrict__ A,
    const float* __restrict__ W0, const float* __restrict__ W1, const float* __restrict__ W2,
    const float* __restrict__ bias0, const float* __restrict__ bias1, const float* __restrict__ bias2,
    float* __restrict__ C0, float* __restrict__ C1, float* __restrict__ C2)
{
    const float* W; const float* bias; float* C;
    if (blockIdx.z == 0)      { W = W0; bias = bias0; C = C0; }
    else if (blockIdx.z == 1) { W = W1; bias = bias1; C = C1; }
    else                      { W = W2; bias = bias2; C = C2; }

    __shared__ float As[16][128];
    __shared__ float Bs[16][128];

    int tid = threadIdx.x;
    int tx = tid & 15;
    int ty = tid >> 4;
    int m0 = blockIdx.y * 128;
    int n0 = blockIdx.x * 128;

    float acc[8][8];
    #pragma unroll
    for (int i = 0; i < 8; ++i)
        #pragma unroll
        for (int j = 0; j < 8; ++j) acc[i][j] = 0.f;

    int lr = tid >> 2;        // 0..63
    int lc = (tid & 3) * 4;   // 0,4,8,12

    for (int kt = 0; kt < HH; kt += 16) {
        #pragma unroll
        for (int p = 0; p < 2; ++p) {
            int row = lr + p * 64;
            float4 av = *(const float4*)(A + (size_t)(m0 + row) * HH + kt + lc);
            As[lc + 0][row] = av.x; As[lc + 1][row] = av.y;
            As[lc + 2][row] = av.z; As[lc + 3][row] = av.w;
            float4 wv = *(const float4*)(W + (size_t)(n0 + row) * HH + kt + lc);
            Bs[lc + 0][row] = wv.x; Bs[lc + 1][row] = wv.y;
            Bs[lc + 2][row] = wv.z; Bs[lc + 3][row] = wv.w;
        }
        __syncthreads();
        #pragma unroll
        for (int k = 0; k < 16; ++k) {
            float a[8], b[8];
            *(float4*)&a[0] = *(const float4*)&As[k][ty * 8];
            *(float4*)&a[4] = *(const float4*)&As[k][ty * 8 + 4];
            *(float4*)&b[0] = *(const float4*)&Bs[k][tx * 8];
            *(float4*)&b[4] = *(const float4*)&Bs[k][tx * 8 + 4];
            #pragma unroll
            for (int i = 0; i < 8; ++i)
                #pragma unroll
                for (int j = 0; j < 8; ++j)
                    acc[i][j] = fmaf(a[i], b[j], acc[i][j]);
        }
        __syncthreads();
    }

    float bv[8];
    #pragma unroll
    for (int j = 0; j < 8; ++j) bv[j] = bias[n0 + tx * 8 + j];

    #pragma unroll
    for (int i = 0; i < 8; ++i) {
        size_t off = (size_t)(m0 + ty * 8 + i) * HH + n0 + tx * 8;
        float4 o0 = make_float4(acc[i][0] + bv[0], acc[i][1] + bv[1],
                                acc[i][2] + bv[2], acc[i][3] + bv[3]);
        float4 o1 = make_float4(acc[i][4] + bv[4], acc[i][5] + bv[5],
                                acc[i][6] + bv[6], acc[i][7] + bv[7]);
        *(float4*)(C + off)     = o0;
        *(float4*)(C + off + 4) = o1;
    }
}

// ---------------------------------------------------------------------------
// Suffix sums of V per (b,h): vsuf[bh][blk][d] = sum_{j >= blk*32} v[b,j,h,d],
// blk in 0..64 (vsuf[64] = 0). 32 CTAs x 256 threads (64 d-lanes x 4 groups).
// ---------------------------------------------------------------------------
__global__ void __launch_bounds__(256) suffix_kernel(const float* __restrict__ v,
                                                     float* __restrict__ vsuf)
{
    int bh = blockIdx.x;          // b*16 + h
    int b = bh >> 4, h = bh & 15;
    int d = threadIdx.x & 63;
    int g = threadIdx.x >> 6;     // 0..3, each owns 512 j's

    __shared__ float ps[4][16][64];

    size_t vbase = (size_t)b * SS * HH + (size_t)h * HD + d;

    float acc = 0.f;
    for (int t = 15; t >= 0; --t) {
        int jbase = g * 512 + t * 32;
        #pragma unroll
        for (int jj = 31; jj >= 0; --jj)
            acc += v[vbase + (size_t)(jbase + jj) * HH];
        ps[g][t][d] = acc;
    }
    __syncthreads();

    float offset = 0.f;
    for (int g2 = g + 1; g2 < 4; ++g2) offset += ps[g2][0][d];

    for (int t = 0; t < 16; ++t) {
        int blk = g * 16 + t;
        vsuf[((size_t)bh * 65 + blk) * HD + d] = ps[g][t][d] + offset;
    }
    if (g == 3)
        vsuf[((size_t)bh * 65 + 64) * HD + d] = 0.f;
}

// ---------------------------------------------------------------------------
// Block-causal attention with zero-score softmax correction.
// Per CTA: 128 queries x one head. Iterates key tiles of 64 up to the tile's
// max limit; per-row mask inside. Adds suffix-V / count correction at the end.
// Dynamic smem: Qs[128][64] Ks[64][65] Vs[64][64] Ps[128][65] dn[128].
// ---------------------------------------------------------------------------
#define ATTN_SMEM_FLOATS (128*64 + 64*65 + 64*64 + 128*65 + 128)
#define ATTN_SMEM_BYTES  (ATTN_SMEM_FLOATS * 4)

__global__ void __launch_bounds__(256) attn_kernel(
    const float* __restrict__ gq, const float* __restrict__ gk,
    const float* __restrict__ gv, const float* __restrict__ vsuf,
    float* __restrict__ gctx)
{
    int qt = (int)gridDim.x - 1 - (int)blockIdx.x;  // heavy tiles first
    int h  = blockIdx.y;
    int b  = blockIdx.z;

    extern __shared__ float sm[];
    float* Qs = sm;                 // [128][64]
    float* Ks = Qs + 128 * 64;      // [64][65]
    float* Vs = Ks + 64 * 65;       // [64][64]
    float* Ps = Vs + 64 * 64;       // [128][65]
    float* dn = Ps + 128 * 65;      // [128]

    int tid = threadIdx.x;
    int tx = tid & 15;              // 16 cols of 4
    int ty = tid >> 4;              // 16 rows of 8
    int m0 = qt * 128;

    size_t base = (size_t)b * SS * HH + (size_t)h * HD;

    // load Q tile
    #pragma unroll
    for (int p = 0; p < 8; ++p) {
        int row = p * 16 + (tid >> 4);
        float4 qv = *(const float4*)(gq + base + (size_t)(m0 + row) * HH + (tid & 15) * 4);
        *(float4*)&Qs[row * 64 + (tid & 15) * 4] = qv;
    }

    float acc[8][4];
    #pragma unroll
    for (int i = 0; i < 8; ++i)
        #pragma unroll
        for (int j = 0; j < 4; ++j) acc[i][j] = 0.f;

    float denom_acc = 0.f;          // owned by tid<128, row = tid

    int nkt = 2 * qt + 2;
    for (int kt = 0; kt < nkt; ++kt) {
        // load K (padded 65) and V tiles
        #pragma unroll
        for (int p = 0; p < 4; ++p) {
            int row = p * 16 + (tid >> 4);
            int j = kt * 64 + row;
            float4 kv = *(const float4*)(gk + base + (size_t)j * HH + (tid & 15) * 4);
            Ks[row * 65 + (tid & 15) * 4 + 0] = kv.x;
            Ks[row * 65 + (tid & 15) * 4 + 1] = kv.y;
            Ks[row * 65 + (tid & 15) * 4 + 2] = kv.z;
            Ks[row * 65 + (tid & 15) * 4 + 3] = kv.w;
            float4 vv = *(const float4*)(gv + base + (size_t)j * HH + (tid & 15) * 4);
            *(float4*)&Vs[row * 64 + (tid & 15) * 4] = vv;
        }
        __syncthreads();

        // GEMM1: S = Q @ K^T (8x4 per thread)
        float s[8][4];
        #pragma unroll
        for (int i = 0; i < 8; ++i)
            #pragma unroll
            for (int j = 0; j < 4; ++j) s[i][j] = 0.f;

        #pragma unroll 4
        for (int d = 0; d < 64; ++d) {
            float a[8], bb[4];
            #pragma unroll
            for (int i = 0; i < 8; ++i) a[i] = Qs[(ty * 8 + i) * 64 + d];
            #pragma unroll
            for (int j = 0; j < 4; ++j) bb[j] = Ks[(tx * 4 + j) * 65 + d];
            #pragma unroll
            for (int i = 0; i < 8; ++i)
                #pragma unroll
                for (int j = 0; j < 4; ++j)
                    s[i][j] = fmaf(a[i], bb[j], s[i][j]);
        }

        // mask + exp -> Ps
        #pragma unroll
        for (int i = 0; i < 8; ++i) {
            int grow = m0 + ty * 8 + i;
            int L = ((grow >> 5) + 1) << 5;
            #pragma unroll
            for (int j = 0; j < 4; ++j) {
                int gj = kt * 64 + tx * 4 + j;
                float p = (gj < L) ? __expf(s[i][j] * 0.125f) : 0.f;
                Ps[(ty * 8 + i) * 65 + tx * 4 + j] = p;
            }
        }
        __syncthreads();

        // denominator partial sums (pad-65 => conflict-free row reads)
        if (tid < 128) {
            float sum = 0.f;
            #pragma unroll 8
            for (int c = 0; c < 64; ++c) sum += Ps[tid * 65 + c];
            denom_acc += sum;
        }

        // GEMM2: acc += P @ V
        #pragma unroll 4
        for (int j = 0; j < 64; ++j) {
            float p[8];
            #pragma unroll
            for (int i = 0; i < 8; ++i) p[i] = Ps[(ty * 8 + i) * 65 + j];
            float4 vv = *(const float4*)&Vs[j * 64 + tx * 4];
            #pragma unroll
            for (int i = 0; i < 8; ++i) {
                acc[i][0] = fmaf(p[i], vv.x, acc[i][0]);
                acc[i][1] = fmaf(p[i], vv.y, acc[i][1]);
                acc[i][2] = fmaf(p[i], vv.z, acc[i][2]);
                acc[i][3] = fmaf(p[i], vv.w, acc[i][3]);
            }
        }
        __syncthreads();   // before next tile overwrites Ks/Vs/Ps
    }

    // finalize denominators (add count of zero-score entries)
    if (tid < 128) {
        int grow = m0 + tid;
        int L = ((grow >> 5) + 1) << 5;
        dn[tid] = denom_acc + (float)(SS - L);
    }
    __syncthreads();

    // suffix-V correction + divide + store
    int bh = b * NH + h;
    int blkp1 = (m0 + ty * 8) / 32 + 1;   // thread's 8 rows share one 32-block
    const float* suf = vsuf + ((size_t)bh * 65 + blkp1) * HD;
    float sufv[4];
    #pragma unroll
    for (int c = 0; c < 4; ++c) sufv[c] = suf[tx * 4 + c];

    #pragma unroll
    for (int i = 0; i < 8; ++i) {
        int grow = m0 + ty * 8 + i;
        float dinv = 1.f / dn[ty * 8 + i];
        float4 o = make_float4((acc[i][0] + sufv[0]) * dinv,
                               (acc[i][1] + sufv[1]) * dinv,
                               (acc[i][2] + sufv[2]) * dinv,
                               (acc[i][3] + sufv[3]) * dinv);
        *(float4*)(gctx + base + (size_t)grow * HH + tx * 4) = o;
    }
}

// ---------------------------------------------------------------------------
extern "C" void kernel_launch(void* const* d_in, const int* in_sizes, int n_in,
                              void* d_out, int out_size)
{
    const float* x  = (const float*)d_in[0];
    const float* Wq = (const float*)d_in[1];
    const float* bq = (const float*)d_in[2];
    const float* Wk = (const float*)d_in[3];
    const float* bk = (const float*)d_in[4];
    const float* Wv = (const float*)d_in[5];
    const float* bv = (const float*)d_in[6];
    const float* Wo = (const float*)d_in[7];
    const float* bo = (const float*)d_in[8];
    float* out = (float*)d_out;

    float *q, *k, *v, *ctx, *vsuf;
    cudaGetSymbolAddress((void**)&q,    g_q);
    cudaGetSymbolAddress((void**)&k,    g_k);
    cudaGetSymbolAddress((void**)&v,    g_v);
    cudaGetSymbolAddress((void**)&ctx,  g_ctx);
    cudaGetSymbolAddress((void**)&vsuf, g_vsuf);

    // 1) fused QKV projections
    gemm_nt_bias<<<dim3(8, 32, 3), 256>>>(x, Wq, Wk, Wv, bq, bk, bv, q, k, v);

    // 2) suffix sums of V
    suffix_kernel<<<32, 256>>>(v, vsuf);

    // 3) block-causal attention with zero-score correction
    cudaFuncSetAttribute(attn_kernel, cudaFuncAttributeMaxDynamicSharedMemorySize,
                         ATTN_SMEM_BYTES);
    attn_kernel<<<dim3(16, NH, BB), 256, ATTN_SMEM_BYTES>>>(q, k, v, vsuf, ctx);

    // 4) output projection -> d_out
    gemm_nt_bias<<<dim3(8, 32, 1), 256>>>(ctx, Wo, Wo, Wo, bo, bo, bo, out, out, out);
}